// round 4
// baseline (speedup 1.0000x reference)
#include <cuda_runtime.h>

#define BATCH 64
#define SEQ   512
#define DIM   300
#define HID   600
#define G4    2400            // 4*HID
#define ROWS  (BATCH*SEQ)     // 32768

// persistent-kernel config
#define GRID_P 120
#define NJ     10             // j-units per block
#define NCOL   40             // 4 gates * NJ columns
#define NT     960            // threads (30 warps)
#define KSPLIT 6
#define KSEG   100            // 600 / KSPLIT
#define ZPAD   42             // padded z row
#define NCELL  (NJ * BATCH)   // 640 gate cells per block
#define BAR_TID 944           // barrier thread (no gate cell)

typedef unsigned long long u64;

// ---------------- packed f32x2 helpers ----------------
__device__ __forceinline__ void ffma2(u64& d, u64 a, u64 b) {
    asm("fma.rn.f32x2 %0, %1, %2, %0;" : "+l"(d) : "l"(a), "l"(b));
}
__device__ __forceinline__ u64 pack2(float lo, float hi) {
    u64 r; asm("mov.b64 %0, {%1, %2};" : "=l"(r) : "f"(lo), "f"(hi)); return r;
}
__device__ __forceinline__ void unpack2(u64 v, float& lo, float& hi) {
    asm("mov.b64 {%0, %1}, %2;" : "=f"(lo), "=f"(hi) : "l"(v));
}

// ---------------- device scratch ----------------
__device__ float g_xw[(size_t)2 * ROWS * G4];   // [dir][row][gatecol]
__device__ float g_UT[2 * G4 * HID];            // [dir][gatecol][k]
__device__ float g_hT[2][2][HID][BATCH];        // [parity][dir][k][b]
__device__ float g_hsum[2 * BATCH * HID];
__device__ unsigned g_cnt2[2];
__device__ unsigned g_rel2[2];

// ---------------- init ----------------
__global__ void k_init() {
    int i = blockIdx.x * blockDim.x + threadIdx.x;
    float* p = &g_hT[0][0][0][0];
    if (i < 2 * 2 * HID * BATCH) p[i] = 0.f;
    if (i < 2) { g_cnt2[i] = 0u; g_rel2[i] = 0u; }
}

// ---------------- transpose U -> UT ----------------
__global__ void k_transpose(const float* __restrict__ Uf, const float* __restrict__ Ub) {
    int i = blockIdx.x * blockDim.x + threadIdx.x;   // over HID*G4
    if (i >= HID * G4) return;
    int k = i / G4, n = i % G4;
    g_UT[n * HID + k]            = Uf[i];
    g_UT[G4 * HID + n * HID + k] = Ub[i];
}

// ---------------- input GEMM: xw = X @ W + b (FFMA2) ----------------
#define BM 128
#define BN 64
#define GBK 12
__global__ __launch_bounds__(256) void k_gemm(const float* __restrict__ X,
                       const float* __restrict__ Wf, const float* __restrict__ bf,
                       const float* __restrict__ Wb, const float* __restrict__ bb) {
    int dir = blockIdx.z;
    const float* W    = dir ? Wb : Wf;
    const float* bias = dir ? bb : bf;
    int m0 = blockIdx.y * BM;
    int n0 = blockIdx.x * BN;
    __shared__ __align__(16) float As[GBK][BM];
    __shared__ __align__(16) float Bs[GBK][BN];
    int tid = threadIdx.x;
    int tx = tid & 15, ty = tid >> 4;
    u64 acc2[4][4] = {};                   // [m-pair][n]
    for (int k0 = 0; k0 < DIM; k0 += GBK) {
        #pragma unroll
        for (int l = 0; l < (BM * GBK) / 256; ++l) {   // 6
            int idx = tid + l * 256;
            int r = idx / GBK, kk = idx % GBK;
            As[kk][r] = X[(size_t)(m0 + r) * DIM + k0 + kk];
        }
        #pragma unroll
        for (int l = 0; l < (BN * GBK) / 256; ++l) {   // 3
            int idx = tid + l * 256;
            int kk = idx / BN, c = idx & (BN - 1);
            int col = n0 + c;
            Bs[kk][c] = (col < G4) ? W[(size_t)(k0 + kk) * G4 + col] : 0.f;
        }
        __syncthreads();
        #pragma unroll
        for (int kk = 0; kk < GBK; ++kk) {
            float4 a0 = *(const float4*)&As[kk][ty * 8];
            float4 a1 = *(const float4*)&As[kk][ty * 8 + 4];
            float4 b4 = *(const float4*)&Bs[kk][tx * 4];
            u64 ap[4] = {pack2(a0.x, a0.y), pack2(a0.z, a0.w),
                         pack2(a1.x, a1.y), pack2(a1.z, a1.w)};
            u64 bp[4] = {pack2(b4.x, b4.x), pack2(b4.y, b4.y),
                         pack2(b4.z, b4.z), pack2(b4.w, b4.w)};
            #pragma unroll
            for (int i = 0; i < 4; i++)
                #pragma unroll
                for (int j = 0; j < 4; j++)
                    ffma2(acc2[i][j], ap[i], bp[j]);
        }
        __syncthreads();
    }
    float* outp = g_xw + (size_t)dir * ROWS * G4;
    #pragma unroll
    for (int i = 0; i < 4; i++) {
        int row = m0 + ty * 8 + 2 * i;
        #pragma unroll
        for (int j = 0; j < 4; j++) {
            int col = n0 + tx * 4 + j;
            if (col < G4) {
                float lo, hi; unpack2(acc2[i][j], lo, hi);
                float bv = bias[col];
                outp[(size_t)row * G4 + col]       = lo + bv;
                outp[(size_t)(row + 1) * G4 + col] = hi + bv;
            }
        }
    }
}

// ---------------- xw prefetch for one (b, jj) cell ----------------
__device__ __forceinline__ void load_xw4(float* px, int s, int b, int jj,
                                         int dir, int j0, int L) {
    bool active = (dir == 0) ? (s < SEQ) : (s < L);
    if (!active) return;
    int trow = (dir == 0) ? s : (L - 1 - s);
    const float* xwr = g_xw + ((size_t)dir * ROWS + b * SEQ + trow) * G4 + (j0 + jj);
    px[0] = xwr[0];
    px[1] = xwr[HID];
    px[2] = xwr[2 * HID];
    px[3] = xwr[3 * HID];
}

// ---------------- persistent recurrence kernel ----------------
__global__ __launch_bounds__(NT, 1) void k_persist(const int* __restrict__ lengths) {
    extern __shared__ __align__(16) float smem[];
    float* u_sh = smem;                    // [HID][NCOL] = 24000 floats
    float* z_sh = smem + HID * NCOL;       // [KSPLIT][64][ZPAD]

    int tid = threadIdx.x;
    int bx  = blockIdx.x;
    int dir = (bx >= 60) ? 1 : 0;
    int j0  = (dir ? bx - 60 : bx) * NJ;

    // load this block's U slice into SMEM (once)
    {
        const float* UT = g_UT + (size_t)dir * G4 * HID;
        for (int idx = tid; idx < NCOL * HID; idx += NT) {
            int c = idx / HID, k = idx % HID;
            int gcol = (c / NJ) * HID + j0 + (c % NJ);
            u_sh[k * NCOL + c] = UT[(size_t)gcol * HID + k];
        }
    }

    // compute mapping: KSPLIT k-segs x 16 b-groups(4) x 10 c-groups(4)
    int kh = tid / 160;
    int r  = tid % 160;
    int bb = (r / 10) * 4;
    int cc = (r % 10) * 4;

    // gate-cell mapping: one cell per thread for tid < NCELL (640)
    int bc = tid & 63;
    int jc = tid >> 6;            // 0..9 for tid < 640
    bool has_cell = (tid < NCELL);
    int L = has_cell ? lengths[bc] : 0;
    float cr = 0.f, hs = 0.f;
    float px[4], nx[4];
    if (has_cell) load_xw4(px, 0, bc, jc, dir, j0, L);

    __syncthreads();

    for (int s = 0; s < SEQ; s++) {
        int rp = s & 1;
        // ---- partial matvec: z[b, c] += h[b, k] * U[k, c] over this k-seg ----
        const float* hp = &g_hT[rp][dir][kh * KSEG][0] + bb;
        const float* up = u_sh + (kh * KSEG) * NCOL + cc;
        u64 acc2[2][4] = {};
        #pragma unroll 4
        for (int k = 0; k < KSEG; k++) {
            float4 h4 = *(const float4*)hp;  hp += BATCH;
            float4 u4 = *(const float4*)up;  up += NCOL;
            u64 hpair[2] = {pack2(h4.x, h4.y), pack2(h4.z, h4.w)};
            u64 ub[4] = {pack2(u4.x, u4.x), pack2(u4.y, u4.y),
                         pack2(u4.z, u4.z), pack2(u4.w, u4.w)};
            #pragma unroll
            for (int i = 0; i < 2; i++)
                #pragma unroll
                for (int j = 0; j < 4; j++)
                    ffma2(acc2[i][j], hpair[i], ub[j]);
        }
        #pragma unroll
        for (int i = 0; i < 2; i++) {
            float* zr0 = z_sh + ((kh * 64) + bb + 2 * i) * ZPAD + cc;
            float* zr1 = zr0 + ZPAD;
            #pragma unroll
            for (int j = 0; j < 4; j++) {
                float lo, hi; unpack2(acc2[i][j], lo, hi);
                zr0[j] = lo; zr1[j] = hi;
            }
        }

        // ---- prefetch next step's xw ----
        if (has_cell) load_xw4(nx, s + 1, bc, jc, dir, j0, L);

        __syncthreads();

        // ---- gate math / state update ----
        if (has_cell) {
            float z0 = 0.f, z1 = 0.f, z2 = 0.f, z3 = 0.f;
            #pragma unroll
            for (int p = 0; p < KSPLIT; p++) {
                const float* zb = z_sh + (p * 64 + bc) * ZPAD;
                z0 += zb[jc];
                z1 += zb[NJ + jc];
                z2 += zb[2 * NJ + jc];
                z3 += zb[3 * NJ + jc];
            }
            bool active = (dir == 0) ? true : (s < L);
            if (active) {
                float zi = z0 + px[0];
                float zf = z1 + px[1];
                float zg = z2 + px[2];
                float zo = z3 + px[3];
                float ig = 1.f / (1.f + __expf(-zi));
                float fg = 1.f / (1.f + __expf(-zf));
                float gg = tanhf(zg);
                float og = 1.f / (1.f + __expf(-zo));
                cr = fg * cr + ig * gg;
                float h = og * tanhf(cr);
                g_hT[rp ^ 1][dir][j0 + jc][bc] = h;
                if (dir == 1 || s < L) hs += h;
                __threadfence();   // release h before barrier arrival
            }
            #pragma unroll
            for (int q = 0; q < 4; q++) px[q] = nx[q];
        }
        __syncthreads();

        // ---- per-direction global barrier ----
        if (tid == BAR_TID) {
            unsigned a = atomicAdd(&g_cnt2[dir], 1u) + 1u;
            if (a == 60u * (unsigned)(s + 1)) {
                __threadfence();
                *(volatile unsigned*)&g_rel2[dir] = (unsigned)(s + 1);
            } else {
                while (*(volatile unsigned*)&g_rel2[dir] < (unsigned)(s + 1)) {}
            }
            __threadfence();   // acquire: invalidate L1 so fresh h is read
        }
        __syncthreads();
    }

    // ---- write per-cell hsum to global ----
    if (has_cell)
        g_hsum[dir * BATCH * HID + bc * HID + j0 + jc] = hs;
}

// ---------------- finalize: mean over T ----------------
__global__ void k_final(float* __restrict__ out) {
    int i = blockIdx.x * blockDim.x + threadIdx.x;
    if (i >= BATCH * 2 * HID) return;
    int b = i / (2 * HID), j = i % (2 * HID);
    float v = (j < HID) ? g_hsum[b * HID + j]
                        : g_hsum[BATCH * HID + b * HID + (j - HID)];
    out[i] = v * (1.0f / SEQ);
}

// ---------------- launch ----------------
extern "C" void kernel_launch(void* const* d_in, const int* in_sizes, int n_in,
                              void* d_out, int out_size) {
    const float *X = nullptr, *Wf = nullptr, *Uf = nullptr, *bf = nullptr;
    const float *Wb = nullptr, *Ub = nullptr, *bb = nullptr;
    const int* lengths = nullptr;
    int cW = 0, cU = 0, cb = 0;
    for (int i = 0; i < n_in; i++) {
        int s = in_sizes[i];
        if      (s == BATCH * SEQ * DIM) X = (const float*)d_in[i];
        else if (s == BATCH)             lengths = (const int*)d_in[i];
        else if (s == DIM * G4)   { if (cW++ == 0) Wf = (const float*)d_in[i]; else Wb = (const float*)d_in[i]; }
        else if (s == HID * G4)   { if (cU++ == 0) Uf = (const float*)d_in[i]; else Ub = (const float*)d_in[i]; }
        else if (s == G4)         { if (cb++ == 0) bf = (const float*)d_in[i]; else bb = (const float*)d_in[i]; }
    }

    static const int smem_bytes = (HID * NCOL + KSPLIT * 64 * ZPAD) * 4;   // 160512
    cudaFuncSetAttribute(k_persist, cudaFuncAttributeMaxDynamicSharedMemorySize, smem_bytes);

    k_init<<<(2 * 2 * HID * BATCH + 255) / 256, 256>>>();
    k_transpose<<<(HID * G4 + 255) / 256, 256>>>(Uf, Ub);
    k_gemm<<<dim3((G4 + BN - 1) / BN, ROWS / BM, 2), 256>>>(X, Wf, bf, Wb, bb);
    k_persist<<<GRID_P, NT, smem_bytes>>>(lengths);
    k_final<<<(BATCH * 2 * HID + 255) / 256, 256>>>((float*)d_out);
}

// round 5
// speedup vs baseline: 1.0255x; 1.0255x over previous
#include <cuda_runtime.h>

#define BATCH 64
#define SEQ   512
#define DIM   300
#define HID   600
#define G4    2400            // 4*HID
#define ROWS  (BATCH*SEQ)     // 32768

// persistent-kernel config
#define GRID_P 120
#define NJ     10             // j-units per block
#define NCOL   40             // 4 gates * NJ columns
#define NT     960            // threads (30 warps)
#define KSPLIT 6
#define ZPAD   42             // padded z row
#define NCELL  (NJ * BATCH)   // 640 gate cells per block
#define BAR_TID 944
#define KC     120            // h chunk rows
#define NCHUNK 5              // 600 / KC
#define KSUB   20             // KC / KSPLIT

typedef unsigned long long u64;

// ---------------- packed f32x2 helpers ----------------
__device__ __forceinline__ void ffma2(u64& d, u64 a, u64 b) {
    asm("fma.rn.f32x2 %0, %1, %2, %0;" : "+l"(d) : "l"(a), "l"(b));
}
__device__ __forceinline__ u64 pack2(float lo, float hi) {
    u64 r; asm("mov.b64 %0, {%1, %2};" : "=l"(r) : "f"(lo), "f"(hi)); return r;
}
__device__ __forceinline__ void unpack2(u64 v, float& lo, float& hi) {
    asm("mov.b64 {%0, %1}, %2;" : "=f"(lo), "=f"(hi) : "l"(v));
}

// ---------------- device scratch ----------------
__device__ float g_xw[(size_t)2 * ROWS * G4];   // [dir][row][gatecol]
__device__ float g_UT[2 * G4 * HID];            // [dir][gatecol][k]
__device__ float g_hT[2][2][HID][BATCH];        // [parity][dir][k][b]
__device__ float g_hsum[2 * BATCH * HID];
__device__ unsigned g_cnt2[2];
__device__ unsigned g_rel2[2];

// ---------------- init ----------------
__global__ void k_init() {
    int i = blockIdx.x * blockDim.x + threadIdx.x;
    float* p = &g_hT[0][0][0][0];
    if (i < 2 * 2 * HID * BATCH) p[i] = 0.f;
    if (i < 2) { g_cnt2[i] = 0u; g_rel2[i] = 0u; }
}

// ---------------- transpose U -> UT ----------------
__global__ void k_transpose(const float* __restrict__ Uf, const float* __restrict__ Ub) {
    int i = blockIdx.x * blockDim.x + threadIdx.x;
    if (i >= HID * G4) return;
    int k = i / G4, n = i % G4;
    g_UT[n * HID + k]            = Uf[i];
    g_UT[G4 * HID + n * HID + k] = Ub[i];
}

// ---------------- input GEMM: xw = X @ W + b (FFMA2) ----------------
#define BM 128
#define BN 64
#define GBK 12
__global__ __launch_bounds__(256) void k_gemm(const float* __restrict__ X,
                       const float* __restrict__ Wf, const float* __restrict__ bf,
                       const float* __restrict__ Wb, const float* __restrict__ bb) {
    int dir = blockIdx.z;
    const float* W    = dir ? Wb : Wf;
    const float* bias = dir ? bb : bf;
    int m0 = blockIdx.y * BM;
    int n0 = blockIdx.x * BN;
    __shared__ __align__(16) float As[GBK][BM];
    __shared__ __align__(16) float Bs[GBK][BN];
    int tid = threadIdx.x;
    int tx = tid & 15, ty = tid >> 4;
    u64 acc2[4][4] = {};
    for (int k0 = 0; k0 < DIM; k0 += GBK) {
        #pragma unroll
        for (int l = 0; l < (BM * GBK) / 256; ++l) {
            int idx = tid + l * 256;
            int r = idx / GBK, kk = idx % GBK;
            As[kk][r] = X[(size_t)(m0 + r) * DIM + k0 + kk];
        }
        #pragma unroll
        for (int l = 0; l < (BN * GBK) / 256; ++l) {
            int idx = tid + l * 256;
            int kk = idx / BN, c = idx & (BN - 1);
            int col = n0 + c;
            Bs[kk][c] = (col < G4) ? W[(size_t)(k0 + kk) * G4 + col] : 0.f;
        }
        __syncthreads();
        #pragma unroll
        for (int kk = 0; kk < GBK; ++kk) {
            float4 a0 = *(const float4*)&As[kk][ty * 8];
            float4 a1 = *(const float4*)&As[kk][ty * 8 + 4];
            float4 b4 = *(const float4*)&Bs[kk][tx * 4];
            u64 ap[4] = {pack2(a0.x, a0.y), pack2(a0.z, a0.w),
                         pack2(a1.x, a1.y), pack2(a1.z, a1.w)};
            u64 bp[4] = {pack2(b4.x, b4.x), pack2(b4.y, b4.y),
                         pack2(b4.z, b4.z), pack2(b4.w, b4.w)};
            #pragma unroll
            for (int i = 0; i < 4; i++)
                #pragma unroll
                for (int j = 0; j < 4; j++)
                    ffma2(acc2[i][j], ap[i], bp[j]);
        }
        __syncthreads();
    }
    float* outp = g_xw + (size_t)dir * ROWS * G4;
    #pragma unroll
    for (int i = 0; i < 4; i++) {
        int row = m0 + ty * 8 + 2 * i;
        #pragma unroll
        for (int j = 0; j < 4; j++) {
            int col = n0 + tx * 4 + j;
            if (col < G4) {
                float lo, hi; unpack2(acc2[i][j], lo, hi);
                float bv = bias[col];
                outp[(size_t)row * G4 + col]       = lo + bv;
                outp[(size_t)(row + 1) * G4 + col] = hi + bv;
            }
        }
    }
}

// ---------------- xw prefetch for one (b, jj) cell ----------------
__device__ __forceinline__ void load_xw4(float* px, int s, int b, int jj,
                                         int dir, int j0, int L) {
    bool active = (dir == 0) ? (s < SEQ) : (s < L);
    if (!active) return;
    int trow = (dir == 0) ? s : (L - 1 - s);
    const float* xwr = g_xw + ((size_t)dir * ROWS + b * SEQ + trow) * G4 + (j0 + jj);
    px[0] = xwr[0];
    px[1] = xwr[HID];
    px[2] = xwr[2 * HID];
    px[3] = xwr[3 * HID];
}

// ---------------- cp.async stage: one h chunk (KC*64 floats) ----------------
__device__ __forceinline__ void stage_chunk(unsigned dst_smem, const float4* hbase4,
                                            int ck, int tid) {
    const float4* src = hbase4 + ck * (KC * 64 / 4);   // 1920 float4 per chunk
    unsigned d0 = dst_smem + tid * 16;
    asm volatile("cp.async.cg.shared.global [%0], [%1], 16;" :: "r"(d0), "l"(src + tid));
    asm volatile("cp.async.cg.shared.global [%0], [%1], 16;"
                 :: "r"(d0 + 960 * 16), "l"(src + tid + 960));
    asm volatile("cp.async.commit_group;" ::: "memory");
}
__device__ __forceinline__ void stage_wait() {
    asm volatile("cp.async.wait_group 0;" ::: "memory");
}

// ---------------- persistent recurrence kernel ----------------
__global__ __launch_bounds__(NT, 1) void k_persist(const int* __restrict__ lengths) {
    extern __shared__ __align__(16) float smem[];
    float* u_sh = smem;                                   // [HID][NCOL] 24000 f
    float* z_sh = smem + HID * NCOL;                      // [KSPLIT][64][ZPAD] 16128 f
    float* h_sh = z_sh + KSPLIT * 64 * ZPAD;              // [2][KC][64] 15360 f

    int tid = threadIdx.x;
    int bx  = blockIdx.x;
    int dir = (bx >= 60) ? 1 : 0;
    int j0  = (dir ? bx - 60 : bx) * NJ;

    unsigned h_sh_addr = (unsigned)__cvta_generic_to_shared(h_sh);

    // load this block's U slice into SMEM (once)
    {
        const float* UT = g_UT + (size_t)dir * G4 * HID;
        for (int idx = tid; idx < NCOL * HID; idx += NT) {
            int c = idx / HID, k = idx % HID;
            int gcol = (c / NJ) * HID + j0 + (c % NJ);
            u_sh[k * NCOL + c] = UT[(size_t)gcol * HID + k];
        }
    }

    // compute mapping: KSPLIT k-subsegs x 16 b-groups(4) x 10 c-groups(4)
    int kh = tid / 160;
    int r  = tid % 160;
    int bb = (r / 10) * 4;
    int cc = (r % 10) * 4;

    // gate-cell mapping
    int bc = tid & 63;
    int jc = tid >> 6;
    bool has_cell = (tid < NCELL);
    int L = has_cell ? lengths[bc] : 0;
    float cr = 0.f, hs = 0.f;
    float px[4], nx[4];
    if (has_cell) load_xw4(px, 0, bc, jc, dir, j0, L);

    __syncthreads();

    for (int s = 0; s < SEQ; s++) {
        int rp = s & 1;
        const float4* hbase4 = (const float4*)&g_hT[rp][dir][0][0];

        // ---- prologue: stage chunk 0 ----
        stage_chunk(h_sh_addr, hbase4, 0, tid);
        stage_wait();
        __syncthreads();

        u64 acc2[2][4] = {};
        #pragma unroll
        for (int ck = 0; ck < NCHUNK; ck++) {
            if (ck < NCHUNK - 1)
                stage_chunk(h_sh_addr + (((ck + 1) & 1) * KC * 64) * 4, hbase4, ck + 1, tid);

            const float* hbuf = h_sh + ((ck & 1) * KC * 64);
            const float* hp = hbuf + (kh * KSUB) * 64 + bb;
            const float* up = u_sh + ((size_t)(ck * KC + kh * KSUB)) * NCOL + cc;
            #pragma unroll 5
            for (int kk = 0; kk < KSUB; kk++) {
                float4 h4 = *(const float4*)hp;  hp += 64;
                float4 u4 = *(const float4*)up;  up += NCOL;
                u64 hpair[2] = {pack2(h4.x, h4.y), pack2(h4.z, h4.w)};
                u64 ub[4] = {pack2(u4.x, u4.x), pack2(u4.y, u4.y),
                             pack2(u4.z, u4.z), pack2(u4.w, u4.w)};
                #pragma unroll
                for (int i = 0; i < 2; i++)
                    #pragma unroll
                    for (int j = 0; j < 4; j++)
                        ffma2(acc2[i][j], hpair[i], ub[j]);
            }
            if (ck == NCHUNK - 1) {
                // write z partials before the loop's final sync
                #pragma unroll
                for (int i = 0; i < 2; i++) {
                    float* zr0 = z_sh + ((kh * 64) + bb + 2 * i) * ZPAD + cc;
                    float* zr1 = zr0 + ZPAD;
                    #pragma unroll
                    for (int j = 0; j < 4; j++) {
                        float lo, hi; unpack2(acc2[i][j], lo, hi);
                        zr0[j] = lo; zr1[j] = hi;
                    }
                }
                // prefetch next step's xw
                if (has_cell) load_xw4(nx, s + 1, bc, jc, dir, j0, L);
            } else {
                stage_wait();
            }
            __syncthreads();
        }

        // ---- gate math / state update ----
        if (has_cell) {
            float z0 = 0.f, z1 = 0.f, z2 = 0.f, z3 = 0.f;
            #pragma unroll
            for (int p = 0; p < KSPLIT; p++) {
                const float* zb = z_sh + (p * 64 + bc) * ZPAD;
                z0 += zb[jc];
                z1 += zb[NJ + jc];
                z2 += zb[2 * NJ + jc];
                z3 += zb[3 * NJ + jc];
            }
            bool active = (dir == 0) ? true : (s < L);
            if (active) {
                float zi = z0 + px[0];
                float zf = z1 + px[1];
                float zg = z2 + px[2];
                float zo = z3 + px[3];
                float ig = 1.f / (1.f + __expf(-zi));
                float fg = 1.f / (1.f + __expf(-zf));
                float gg = tanhf(zg);
                float og = 1.f / (1.f + __expf(-zo));
                cr = fg * cr + ig * gg;
                float h = og * tanhf(cr);
                g_hT[rp ^ 1][dir][j0 + jc][bc] = h;
                if (dir == 1 || s < L) hs += h;
            }
            #pragma unroll
            for (int q = 0; q < 4; q++) px[q] = nx[q];
        }
        __syncthreads();

        // ---- per-direction global barrier ----
        if (tid == BAR_TID) {
            __threadfence();
            unsigned a = atomicAdd(&g_cnt2[dir], 1u) + 1u;
            if (a == 60u * (unsigned)(s + 1)) {
                __threadfence();
                *(volatile unsigned*)&g_rel2[dir] = (unsigned)(s + 1);
            } else {
                while (*(volatile unsigned*)&g_rel2[dir] < (unsigned)(s + 1)) {}
            }
            __threadfence();   // acquire: flush L1 so fresh h is read next step
        }
        __syncthreads();
    }

    // ---- write per-cell hsum to global ----
    if (has_cell)
        g_hsum[dir * BATCH * HID + bc * HID + j0 + jc] = hs;
}

// ---------------- finalize: mean over T ----------------
__global__ void k_final(float* __restrict__ out) {
    int i = blockIdx.x * blockDim.x + threadIdx.x;
    if (i >= BATCH * 2 * HID) return;
    int b = i / (2 * HID), j = i % (2 * HID);
    float v = (j < HID) ? g_hsum[b * HID + j]
                        : g_hsum[BATCH * HID + b * HID + (j - HID)];
    out[i] = v * (1.0f / SEQ);
}

// ---------------- launch ----------------
extern "C" void kernel_launch(void* const* d_in, const int* in_sizes, int n_in,
                              void* d_out, int out_size) {
    const float *X = nullptr, *Wf = nullptr, *Uf = nullptr, *bf = nullptr;
    const float *Wb = nullptr, *Ub = nullptr, *bb = nullptr;
    const int* lengths = nullptr;
    int cW = 0, cU = 0, cb = 0;
    for (int i = 0; i < n_in; i++) {
        int s = in_sizes[i];
        if      (s == BATCH * SEQ * DIM) X = (const float*)d_in[i];
        else if (s == BATCH)             lengths = (const int*)d_in[i];
        else if (s == DIM * G4)   { if (cW++ == 0) Wf = (const float*)d_in[i]; else Wb = (const float*)d_in[i]; }
        else if (s == HID * G4)   { if (cU++ == 0) Uf = (const float*)d_in[i]; else Ub = (const float*)d_in[i]; }
        else if (s == G4)         { if (cb++ == 0) bf = (const float*)d_in[i]; else bb = (const float*)d_in[i]; }
    }

    static const int smem_bytes =
        (HID * NCOL + KSPLIT * 64 * ZPAD + 2 * KC * 64) * 4;   // 221952
    cudaFuncSetAttribute(k_persist, cudaFuncAttributeMaxDynamicSharedMemorySize, smem_bytes);

    k_init<<<(2 * 2 * HID * BATCH + 255) / 256, 256>>>();
    k_transpose<<<(HID * G4 + 255) / 256, 256>>>(Uf, Ub);
    k_gemm<<<dim3((G4 + BN - 1) / BN, ROWS / BM, 2), 256>>>(X, Wf, bf, Wb, bb);
    k_persist<<<GRID_P, NT, smem_bytes>>>(lengths);
    k_final<<<(BATCH * 2 * HID + 255) / 256, 256>>>((float*)d_out);
}